// round 16
// baseline (speedup 1.0000x reference)
#include <cuda_runtime.h>
#include <cuda_fp16.h>
#include <cstdint>
#include <math.h>

// Problem constants
constexpr int B  = 4;
constexpr int N  = 2048;
constexpr int D  = 1024;
constexpr int H  = 16;
constexpr int DK = 64;
constexpr int HD = H * DK;   // 1024

constexpr float QSCALE = 0.125f * 1.4426950408889634f;  // 1/sqrt(DK) * log2(e)

// ---------------------------------------------------------------------------
// Scratch (device globals — no allocation allowed). fp16 storage.
// Q pre-scaled by QSCALE (attention logits computed in log2 domain -> exp2).
// ---------------------------------------------------------------------------
__device__ __half g_Qhi[(size_t)B * H * N * DK];
__device__ __half g_Khi[(size_t)B * H * N * DK];
__device__ __half g_Vhi[(size_t)B * H * N * DK];
__device__ __half g_Xhi[(size_t)B * N * D];       // X fp16, [m][k]
__device__ __half g_WThi[4][(size_t)D * HD];      // W^T fp16, [n][k] (0=q,1=k,2=v,3=o)
__device__ __half g_AThi[(size_t)B * N * HD];     // attention out split, [m][k]
__device__ __half g_ATlo[(size_t)B * N * HD];

// ---------------------------------------------------------------------------
// PTX helpers (generic sm_80+ path — harness PTX targets compute_103, which
// rejects tcgen05/'a'-suffix features; legacy HMMA/ldmatrix/cp.async only)
// ---------------------------------------------------------------------------
__device__ __forceinline__ uint32_t smem_u32(const void* p) {
    uint32_t a;
    asm("{ .reg .u64 t; cvta.to.shared.u64 t, %1; cvt.u32.u64 %0, t; }" : "=r"(a) : "l"(p));
    return a;
}
__device__ __forceinline__ void cp16(uint32_t dst, const void* src) {
    asm volatile("cp.async.cg.shared.global [%0], [%1], 16;" :: "r"(dst), "l"(src));
}
#define CP_COMMIT() asm volatile("cp.async.commit_group;" ::: "memory")
#define CP_WAIT(n)  asm volatile("cp.async.wait_group %0;" :: "n"(n) : "memory")

__device__ __forceinline__ void ldsm4(uint32_t& r0, uint32_t& r1, uint32_t& r2, uint32_t& r3,
                                      uint32_t addr) {
    asm volatile("ldmatrix.sync.aligned.m8n8.x4.shared.b16 {%0,%1,%2,%3}, [%4];"
                 : "=r"(r0), "=r"(r1), "=r"(r2), "=r"(r3) : "r"(addr));
}
__device__ __forceinline__ void ldsm4t(uint32_t& r0, uint32_t& r1, uint32_t& r2, uint32_t& r3,
                                       uint32_t addr) {
    asm volatile("ldmatrix.sync.aligned.m8n8.x4.trans.shared.b16 {%0,%1,%2,%3}, [%4];"
                 : "=r"(r0), "=r"(r1), "=r"(r2), "=r"(r3) : "r"(addr));
}
// fp16 inputs, fp32 accumulate
__device__ __forceinline__ void mma16816(float* c,
                                         uint32_t a0, uint32_t a1, uint32_t a2, uint32_t a3,
                                         uint32_t b0, uint32_t b1) {
    asm volatile("mma.sync.aligned.m16n8k16.row.col.f32.f16.f16.f32 "
                 "{%0,%1,%2,%3}, {%4,%5,%6,%7}, {%8,%9}, {%0,%1,%2,%3};"
                 : "+f"(c[0]), "+f"(c[1]), "+f"(c[2]), "+f"(c[3])
                 : "r"(a0), "r"(a1), "r"(a2), "r"(a3), "r"(b0), "r"(b1));
}
__device__ __forceinline__ uint32_t packsplit(float v0, float v1, uint32_t& lo) {
    __half2 hp = __floats2half2_rn(v0, v1);
    float2 hf = __half22float2(hp);
    __half2 lp = __floats2half2_rn(v0 - hf.x, v1 - hf.y);
    lo = *reinterpret_cast<uint32_t*>(&lp);
    return *reinterpret_cast<uint32_t*>(&hp);
}
__device__ __forceinline__ uint32_t packh2(float v0, float v1) {
    __half2 hp = __floats2half2_rn(v0, v1);
    return *reinterpret_cast<uint32_t*>(&hp);
}

// ---------------------------------------------------------------------------
// fp16 HMMA GEMM body, 128x256 CTA tile: C = (Ah [+ Al]) @ Bh.
// A staged via cp.async+ldsm; B fragments loaded DIRECTLY from gmem with
// LDG.32 in the exact m16n8k16 B register layout:
//   b0(lane l) = B^T[n0 + l/4][k + 2(l%4)],  b1 = same at k+8.
// This removes the 256-row B smem stream that made the 2-product qkv
// LDGSTS-issue-bound (3072 cyc LSU vs 2048 tensor per chunk/SMSP).
// B LDGs issue before the next stage's cp.async burst -> L2 latency covered.
// 8 warps as 2m x 4n (warp tile 64x64). 4-stage A ring. f32 accumulate.
// ---------------------------------------------------------------------------
constexpr int APITCH_B = 80;

template <bool USE_AL>
__device__ __forceinline__ void gemm_mma_body(
    const __half* __restrict__ Ahi, const __half* __restrict__ Alo,
    const __half* __restrict__ Bt,
    int rowBase, int colBase, char* sm, float acc[4][8][4])
{
    constexpr int SROWS   = USE_AL ? 256 : 128;   // Ah(128) [| Al(128)]
    constexpr int AL_OFF  = 128 * APITCH_B;
    constexpr int STAGE_B = SROWS * APITCH_B;
    constexpr int NT      = SROWS / 64;

    const int tid  = threadIdx.x;
    const int lane = tid & 31;
    const int w    = tid >> 5;
    const int wm   = (w >> 2) * 64;
    const int wn   = (w & 3) * 64;
    const uint32_t sb = smem_u32(sm);

    // per-lane B fragment base: n = colBase + wn + lane/4, k = (lane&3)*2
    const __half* Bbase = Bt + (size_t)(colBase + wn + (lane >> 2)) * D + (lane & 3) * 2;

    auto load_stage = [&](int s, int k0) {
        const uint32_t base = sb + s * STAGE_B;
        #pragma unroll
        for (int t = 0; t < NT; ++t) {
            const int idx = t * 256 + tid;
            const int r = idx >> 2, ch = idx & 3;
            const __half* src = (r < 128) ? Ahi : Alo;
            const int grow = rowBase + (r & 127);
            cp16(base + r * APITCH_B + ch * 16, src + (size_t)grow * D + k0 + ch * 8);
        }
    };

    constexpr int NC = D / 32;   // 32 chunks
    load_stage(0, 0);            CP_COMMIT();
    load_stage(1, 32);           CP_COMMIT();
    load_stage(2, 64);           CP_COMMIT();

    for (int c = 0; c < NC; ++c) {
        CP_WAIT(2);
        __syncthreads();

        // ---- B fragments for this chunk (direct LDG, 32 regs) ----
        const int kc = c * 32;
        uint32_t Bf[2][4][4];
        #pragma unroll
        for (int k16 = 0; k16 < 2; ++k16)
            #pragma unroll
            for (int np = 0; np < 4; ++np) {
                const __half* p = Bbase + (size_t)(np * 16) * D + kc + k16 * 16;
                Bf[k16][np][0] = *reinterpret_cast<const uint32_t*>(p);
                Bf[k16][np][1] = *reinterpret_cast<const uint32_t*>(p + 8);
                Bf[k16][np][2] = *reinterpret_cast<const uint32_t*>(p + (size_t)8 * D);
                Bf[k16][np][3] = *reinterpret_cast<const uint32_t*>(p + (size_t)8 * D + 8);
            }

        // prefetch A stage c+3 (issue burst also covers the B LDG latency)
        if (c + 3 < NC) load_stage((c + 3) & 3, (c + 3) * 32);
        CP_COMMIT();

        // ---- compute chunk c ----
        const uint32_t base = sb + (c & 3) * STAGE_B;
        #pragma unroll
        for (int k16 = 0; k16 < 2; ++k16) {
            uint32_t Ah[4][4], Al[4][4];
            #pragma unroll
            for (int mi = 0; mi < 4; ++mi) {
                const uint32_t addr = base + (wm + mi * 16 + (lane & 15)) * APITCH_B
                                      + k16 * 32 + (lane >> 4) * 16;
                ldsm4(Ah[mi][0], Ah[mi][1], Ah[mi][2], Ah[mi][3], addr);
                if (USE_AL)
                    ldsm4(Al[mi][0], Al[mi][1], Al[mi][2], Al[mi][3], addr + AL_OFF);
            }
            #pragma unroll
            for (int np = 0; np < 4; ++np) {
                #pragma unroll
                for (int mi = 0; mi < 4; ++mi)
                    #pragma unroll
                    for (int h2 = 0; h2 < 2; ++h2)
                        mma16816(acc[mi][np * 2 + h2],
                                 Ah[mi][0], Ah[mi][1], Ah[mi][2], Ah[mi][3],
                                 Bf[k16][np][h2 * 2], Bf[k16][np][h2 * 2 + 1]);
                if (USE_AL) {
                    #pragma unroll
                    for (int mi = 0; mi < 4; ++mi)
                        #pragma unroll
                        for (int h2 = 0; h2 < 2; ++h2)
                            mma16816(acc[mi][np * 2 + h2],
                                     Al[mi][0], Al[mi][1], Al[mi][2], Al[mi][3],
                                     Bf[k16][np][h2 * 2], Bf[k16][np][h2 * 2 + 1]);
                }
            }
        }
    }
}

constexpr int GSMEM_QKV = 4 * 128 * APITCH_B;   // 40960
constexpr int GSMEM_OUT = 4 * 256 * APITCH_B;   // 81920

// QKV projection (1-product fp16, 128x256 tiles, direct-B).
__global__ __launch_bounds__(256, 1) void qkv_mma() {
    extern __shared__ char sm[];
    const int z = blockIdx.z;
    const int rowBase = blockIdx.y * 128, colBase = blockIdx.x * 256;
    float acc[4][8][4];
    #pragma unroll
    for (int i = 0; i < 4; ++i)
        #pragma unroll
        for (int j = 0; j < 8; ++j)
            #pragma unroll
            for (int k = 0; k < 4; ++k) acc[i][j][k] = 0.f;

    gemm_mma_body<false>(g_Xhi, nullptr, g_WThi[z], rowBase, colBase, sm, acc);

    __half* Out = (z == 0) ? g_Qhi : (z == 1) ? g_Khi : g_Vhi;
    const float scale = (z == 0) ? QSCALE : 1.0f;
    const int lane = threadIdx.x & 31, w = threadIdx.x >> 5;
    const int wm = (w >> 2) * 64, wn = (w & 3) * 64;
    #pragma unroll
    for (int mi = 0; mi < 4; ++mi)
        #pragma unroll
        for (int nf = 0; nf < 8; ++nf) {
            const int r0 = rowBase + wm + mi * 16 + (lane >> 2);
            const int c0 = colBase + wn + nf * 8 + (lane & 3) * 2;
            const int hh = c0 >> 6, dd = c0 & 63;
            #pragma unroll
            for (int rr = 0; rr < 2; ++rr) {
                const int r = r0 + rr * 8;
                const int b = r >> 11, n = r & (N - 1);
                const size_t idx = (((size_t)(b * H + hh)) * N + n) * DK + dd;
                *reinterpret_cast<uint32_t*>(Out + idx) =
                    packh2(acc[mi][nf][rr * 2] * scale, acc[mi][nf][rr * 2 + 1] * scale);
            }
        }
}

// Output projection (2-product, AT-corrected, direct-B): (AThi+ATlo)@Wo -> fp32
__global__ __launch_bounds__(256, 1) void out_mma(float* __restrict__ Cout) {
    extern __shared__ char sm[];
    const int rowBase = blockIdx.y * 128, colBase = blockIdx.x * 256;
    float acc[4][8][4];
    #pragma unroll
    for (int i = 0; i < 4; ++i)
        #pragma unroll
        for (int j = 0; j < 8; ++j)
            #pragma unroll
            for (int k = 0; k < 4; ++k) acc[i][j][k] = 0.f;

    gemm_mma_body<true>(g_AThi, g_ATlo, g_WThi[3], rowBase, colBase, sm, acc);

    const int lane = threadIdx.x & 31, w = threadIdx.x >> 5;
    const int wm = (w >> 2) * 64, wn = (w & 3) * 64;
    #pragma unroll
    for (int mi = 0; mi < 4; ++mi)
        #pragma unroll
        for (int nf = 0; nf < 8; ++nf) {
            const int r0 = rowBase + wm + mi * 16 + (lane >> 2);
            const int c0 = colBase + wn + nf * 8 + (lane & 3) * 2;
            #pragma unroll
            for (int e = 0; e < 4; ++e)
                Cout[(size_t)(r0 + (e >> 1) * 8) * HD + c0 + (e & 1)] = acc[mi][nf][e];
        }
}

// ---------------------------------------------------------------------------
// Conversion passes
// ---------------------------------------------------------------------------
__global__ void convX(const float* __restrict__ X) {
    const size_t i = ((size_t)blockIdx.x * 256 + threadIdx.x) * 4;
    const float4 v = *(const float4*)(X + i);
    uint2 pk; pk.x = packh2(v.x, v.y); pk.y = packh2(v.z, v.w);
    *reinterpret_cast<uint2*>(g_Xhi + i) = pk;
}

// Transpose W -> WT[n][k], fp16
__global__ void convW(const float* __restrict__ Wq, const float* __restrict__ Wk,
                      const float* __restrict__ Wv, const float* __restrict__ Wo) {
    const int z = blockIdx.z;
    const float* W = (z == 0) ? Wq : (z == 1) ? Wk : (z == 2) ? Wv : Wo;
    __half* Th = g_WThi[z];
    __shared__ float t[32][33];
    const int k0 = blockIdx.x * 32, n0 = blockIdx.y * 32;
    #pragma unroll
    for (int j = 0; j < 32; j += 8)
        t[threadIdx.y + j][threadIdx.x] = W[(size_t)(k0 + threadIdx.y + j) * HD + n0 + threadIdx.x];
    __syncthreads();
    #pragma unroll
    for (int j = 0; j < 32; j += 8) {
        const int n = n0 + threadIdx.y + j, k = k0 + threadIdx.x;
        Th[(size_t)n * D + k] = __float2half_rn(t[threadIdx.x][threadIdx.y + j]);
    }
}

// ---------------------------------------------------------------------------
// Tensor-core flash attention (causal):
// S = Qh*Kh (1-product; Q pre-scaled by log2e/8 -> logits in log2 domain).
// Softmax via exp2f (no per-element log2e multiply).
// O = Ph*Vh + Pl*Vh (2-product — 1-product PV exposed trans-LDSM latency
//   at 2 warps/SMSP; R12 regression).
// 128 q-rows per CTA, 8 warps. 3-stage KV ring (Kh|Vh), f32 acc.
// ---------------------------------------------------------------------------
constexpr int FP     = 144;            // smem pitch (128B data + 16B pad)
constexpr int KVARR  = 64 * FP;        // 9216
constexpr int KVSTG  = 2 * KVARR;      // Kh|Vh: 18432
constexpr int QARR   = 128 * FP;       // 18432
constexpr int FSTAGES = 3;
constexpr int FSMEM  = QARR + FSTAGES * KVSTG;   // 73728

__global__ __launch_bounds__(256, 1)
void flash_mma() {
    extern __shared__ char sm[];
    const uint32_t sb = smem_u32(sm);
    const int tid = threadIdx.x, lane = tid & 31, w = tid >> 5;
    const int bh = blockIdx.y;
    const int qt = gridDim.x - 1 - blockIdx.x;        // long blocks first
    const int q0 = qt * 128;
    const int b = bh >> 4, h = bh & (H - 1);
    const int wm = w * 16;

    const __half* Qh = g_Qhi + (size_t)bh * N * DK;
    const __half* Kh = g_Khi + (size_t)bh * N * DK;
    const __half* Vh = g_Vhi + (size_t)bh * N * DK;

    const uint32_t qhiS = sb, stS = sb + QARR;

    auto load_kv = [&](int s, int j0) {
        const uint32_t base = stS + s * KVSTG;
        #pragma unroll
        for (int t = 0; t < 2; ++t) {
            const int i = tid + t * 256;
            const int r = i >> 3, ch = i & 7;
            const uint32_t off = r * FP + ch * 16;
            const size_t gi = (size_t)(j0 + r) * DK + ch * 8;
            cp16(base + off,         Kh + gi);
            cp16(base + KVARR + off, Vh + gi);
        }
    };

    const int jmax = 2 * qt + 1;

    for (int i = tid; i < 1024; i += 256) {
        const int r = i >> 3, ch = i & 7;
        cp16(qhiS + r * FP + ch * 16, Qh + (size_t)(q0 + r) * DK + ch * 8);
    }
    load_kv(0, 0);
    CP_COMMIT();
    load_kv(1, 64);
    CP_COMMIT();

    float m0 = -1e30f, m1 = -1e30f, l0 = 0.f, l1 = 0.f;
    float oAcc[8][4];
    #pragma unroll
    for (int i = 0; i < 8; ++i)
        #pragma unroll
        for (int e = 0; e < 4; ++e) oAcc[i][e] = 0.f;

    uint32_t qah[4][4];
    bool qloaded = false;
    int kvbuf = 0;

    for (int jt = 0; jt <= jmax; ++jt) {
        const int j0 = jt * 64;
        CP_WAIT(1);
        __syncthreads();
        if (jt + 2 <= jmax) {
            int nb = kvbuf + 2; if (nb >= 3) nb -= 3;
            load_kv(nb, (jt + 2) * 64);
        }
        CP_COMMIT();

        if (!qloaded) {
            #pragma unroll
            for (int kf = 0; kf < 4; ++kf) {
                const uint32_t addr = qhiS + (wm + (lane & 15)) * FP + kf * 32 + (lane >> 4) * 16;
                ldsm4(qah[kf][0], qah[kf][1], qah[kf][2], qah[kf][3], addr);
            }
            qloaded = true;
        }

        const uint32_t khS = stS + kvbuf * KVSTG;
        const uint32_t vhS = khS + KVARR;
        if (++kvbuf == 3) kvbuf = 0;

        // ---- S = Qh @ Kh^T (1-product, log2-domain logits) ----
        float s[8][4];
        #pragma unroll
        for (int i = 0; i < 8; ++i)
            #pragma unroll
            for (int e = 0; e < 4; ++e) s[i][e] = 0.f;

        #pragma unroll
        for (int kf = 0; kf < 4; ++kf) {
            uint32_t kb[4][4];
            #pragma unroll
            for (int ng = 0; ng < 4; ++ng) {
                const uint32_t addr = khS + (ng * 16 + (lane & 7) + ((lane >> 4) << 3)) * FP
                                      + kf * 32 + ((lane >> 3) & 1) * 16;
                ldsm4(kb[ng][0], kb[ng][1], kb[ng][2], kb[ng][3], addr);
            }
            #pragma unroll
            for (int ng = 0; ng < 4; ++ng)
                #pragma unroll
                for (int nf = 0; nf < 2; ++nf)
                    mma16816(s[ng * 2 + nf], qah[kf][0], qah[kf][1], qah[kf][2], qah[kf][3],
                             kb[ng][nf * 2], kb[ng][nf * 2 + 1]);
        }

        // ---- causal mask ----
        const int gr0 = q0 + wm + (lane >> 2);
        if (j0 + 64 > q0 + wm) {
            #pragma unroll
            for (int ni = 0; ni < 8; ++ni)
                #pragma unroll
                for (int e = 0; e < 4; ++e) {
                    const int col = j0 + ni * 8 + (lane & 3) * 2 + (e & 1);
                    const int row = gr0 + (e >> 1) * 8;
                    if (col > row) s[ni][e] = -1e30f;
                }
        }

        // ---- online softmax (exp2 domain) ----
        float rm0 = -1e30f, rm1 = -1e30f;
        #pragma unroll
        for (int ni = 0; ni < 8; ++ni) {
            rm0 = fmaxf(rm0, fmaxf(s[ni][0], s[ni][1]));
            rm1 = fmaxf(rm1, fmaxf(s[ni][2], s[ni][3]));
        }
        rm0 = fmaxf(rm0, __shfl_xor_sync(0xffffffffu, rm0, 1));
        rm0 = fmaxf(rm0, __shfl_xor_sync(0xffffffffu, rm0, 2));
        rm1 = fmaxf(rm1, __shfl_xor_sync(0xffffffffu, rm1, 1));
        rm1 = fmaxf(rm1, __shfl_xor_sync(0xffffffffu, rm1, 2));

        const float mn0 = fmaxf(m0, rm0), mn1 = fmaxf(m1, rm1);
        const float a0 = exp2f(m0 - mn0), a1 = exp2f(m1 - mn1);
        m0 = mn0; m1 = mn1;

        float rs0 = 0.f, rs1 = 0.f;
        #pragma unroll
        for (int ni = 0; ni < 8; ++ni) {
            s[ni][0] = exp2f(s[ni][0] - mn0); rs0 += s[ni][0];
            s[ni][1] = exp2f(s[ni][1] - mn0); rs0 += s[ni][1];
            s[ni][2] = exp2f(s[ni][2] - mn1); rs1 += s[ni][2];
            s[ni][3] = exp2f(s[ni][3] - mn1); rs1 += s[ni][3];
        }
        rs0 += __shfl_xor_sync(0xffffffffu, rs0, 1);
        rs0 += __shfl_xor_sync(0xffffffffu, rs0, 2);
        rs1 += __shfl_xor_sync(0xffffffffu, rs1, 1);
        rs1 += __shfl_xor_sync(0xffffffffu, rs1, 2);
        l0 = l0 * a0 + rs0;
        l1 = l1 * a1 + rs1;

        #pragma unroll
        for (int ni = 0; ni < 8; ++ni) {
            oAcc[ni][0] *= a0; oAcc[ni][1] *= a0;
            oAcc[ni][2] *= a1; oAcc[ni][3] *= a1;
        }

        // ---- P -> fp16 hi/lo A-fragments (register-only) ----
        uint32_t pah[4][4], pal[4][4];
        #pragma unroll
        for (int kf = 0; kf < 4; ++kf) {
            pah[kf][0] = packsplit(s[2 * kf][0],     s[2 * kf][1],     pal[kf][0]);
            pah[kf][1] = packsplit(s[2 * kf][2],     s[2 * kf][3],     pal[kf][1]);
            pah[kf][2] = packsplit(s[2 * kf + 1][0], s[2 * kf + 1][1], pal[kf][2]);
            pah[kf][3] = packsplit(s[2 * kf + 1][2], s[2 * kf + 1][3], pal[kf][3]);
        }

        // ---- O += (Ph + Pl) @ Vh ----
        #pragma unroll
        for (int kf = 0; kf < 4; ++kf) {
            uint32_t vb[4][4];
            #pragma unroll
            for (int ng = 0; ng < 4; ++ng) {
                const uint32_t addr = vhS + (kf * 16 + (lane & 15)) * FP
                                      + ng * 32 + (lane >> 4) * 16;
                ldsm4t(vb[ng][0], vb[ng][1], vb[ng][2], vb[ng][3], addr);
            }
            #pragma unroll
            for (int ng = 0; ng < 4; ++ng)
                #pragma unroll
                for (int nf = 0; nf < 2; ++nf)
                    mma16816(oAcc[ng * 2 + nf], pah[kf][0], pah[kf][1], pah[kf][2], pah[kf][3],
                             vb[ng][nf * 2], vb[ng][nf * 2 + 1]);
            #pragma unroll
            for (int ng = 0; ng < 4; ++ng)
                #pragma unroll
                for (int nf = 0; nf < 2; ++nf)
                    mma16816(oAcc[ng * 2 + nf], pal[kf][0], pal[kf][1], pal[kf][2], pal[kf][3],
                             vb[ng][nf * 2], vb[ng][nf * 2 + 1]);
        }
        // no trailing sync: 3-stage ring + top-of-loop barrier covers reuse
    }

    // ---- epilogue: normalize, split to fp16 hi/lo for output projection ----
    const float inv0 = 1.0f / l0, inv1 = 1.0f / l1;
    const int r0 = q0 + wm + (lane >> 2);
    #pragma unroll
    for (int ni = 0; ni < 8; ++ni) {
        const int col = h * DK + ni * 8 + (lane & 3) * 2;
        uint32_t lo;
        uint32_t hi = packsplit(oAcc[ni][0] * inv0, oAcc[ni][1] * inv0, lo);
        size_t idx = ((size_t)b * N + r0) * HD + col;
        *reinterpret_cast<uint32_t*>(g_AThi + idx) = hi;
        *reinterpret_cast<uint32_t*>(g_ATlo + idx) = lo;
        hi = packsplit(oAcc[ni][2] * inv1, oAcc[ni][3] * inv1, lo);
        idx = ((size_t)b * N + r0 + 8) * HD + col;
        *reinterpret_cast<uint32_t*>(g_AThi + idx) = hi;
        *reinterpret_cast<uint32_t*>(g_ATlo + idx) = lo;
    }
}

// ---------------------------------------------------------------------------
extern "C" void kernel_launch(void* const* d_in, const int* in_sizes, int n_in,
                              void* d_out, int out_size) {
    const float* X  = (const float*)d_in[0];
    // d_in[1] = mask (pure causal -> applied analytically)
    const float* Wq = (const float*)d_in[2];
    const float* Wk = (const float*)d_in[3];
    const float* Wv = (const float*)d_in[4];
    const float* Wo = (const float*)d_in[5];
    float* out = (float*)d_out;

    cudaFuncSetAttribute(qkv_mma,   cudaFuncAttributeMaxDynamicSharedMemorySize, GSMEM_QKV);
    cudaFuncSetAttribute(out_mma,   cudaFuncAttributeMaxDynamicSharedMemorySize, GSMEM_OUT);
    cudaFuncSetAttribute(flash_mma, cudaFuncAttributeMaxDynamicSharedMemorySize, FSMEM);

    // 0) conversions
    convX<<<(B * N * D / 4) / 256, 256>>>(X);
    convW<<<dim3(D / 32, HD / 32, 4), dim3(32, 8)>>>(Wq, Wk, Wv, Wo);

    // 1) QKV projections (1-product fp16, 128x256 tiles, direct-B LDG)
    qkv_mma<<<dim3(HD / 256, (B * N) / 128, 3), 256, GSMEM_QKV>>>();   // (4, 64, 3)

    // 2) causal flash attention (S 1-product + exp2, PV 2-product)
    flash_mma<<<dim3(N / 128, B * H), 256, FSMEM>>>();                 // (16, 64)

    // 3) output projection (2-product, AT-corrected, direct-B LDG)
    out_mma<<<dim3(HD / 256, (B * N) / 128), 256, GSMEM_OUT>>>(out);   // (4, 64)
}

// round 17
// speedup vs baseline: 1.3453x; 1.3453x over previous
#include <cuda_runtime.h>
#include <cuda_fp16.h>
#include <cstdint>
#include <math.h>

// Problem constants
constexpr int B  = 4;
constexpr int N  = 2048;
constexpr int D  = 1024;
constexpr int H  = 16;
constexpr int DK = 64;
constexpr int HD = H * DK;   // 1024

constexpr float QSCALE = 0.125f * 1.4426950408889634f;  // 1/sqrt(DK) * log2(e)

// ---------------------------------------------------------------------------
// Scratch (device globals — no allocation allowed). fp16 storage.
// Q pre-scaled by QSCALE (attention logits in log2 domain -> exp2 softmax).
// ---------------------------------------------------------------------------
__device__ __half g_Qhi[(size_t)B * H * N * DK];
__device__ __half g_Khi[(size_t)B * H * N * DK];
__device__ __half g_Vhi[(size_t)B * H * N * DK];
__device__ __half g_Xhi[(size_t)B * N * D];       // X fp16, [m][k]
__device__ __half g_WThi[4][(size_t)D * HD];      // W^T fp16, [n][k] (0=q,1=k,2=v,3=o)
__device__ __half g_AThi[(size_t)B * N * HD];     // attention out split, [m][k]
__device__ __half g_ATlo[(size_t)B * N * HD];

// ---------------------------------------------------------------------------
// PTX helpers (generic sm_80+ path — harness PTX targets compute_103, which
// rejects tcgen05/'a'-suffix features; legacy HMMA/ldmatrix/cp.async only)
// ---------------------------------------------------------------------------
__device__ __forceinline__ uint32_t smem_u32(const void* p) {
    uint32_t a;
    asm("{ .reg .u64 t; cvta.to.shared.u64 t, %1; cvt.u32.u64 %0, t; }" : "=r"(a) : "l"(p));
    return a;
}
__device__ __forceinline__ void cp16(uint32_t dst, const void* src) {
    asm volatile("cp.async.cg.shared.global [%0], [%1], 16;" :: "r"(dst), "l"(src));
}
#define CP_COMMIT() asm volatile("cp.async.commit_group;" ::: "memory")
#define CP_WAIT(n)  asm volatile("cp.async.wait_group %0;" :: "n"(n) : "memory")

__device__ __forceinline__ void ldsm4(uint32_t& r0, uint32_t& r1, uint32_t& r2, uint32_t& r3,
                                      uint32_t addr) {
    asm volatile("ldmatrix.sync.aligned.m8n8.x4.shared.b16 {%0,%1,%2,%3}, [%4];"
                 : "=r"(r0), "=r"(r1), "=r"(r2), "=r"(r3) : "r"(addr));
}
__device__ __forceinline__ void ldsm4t(uint32_t& r0, uint32_t& r1, uint32_t& r2, uint32_t& r3,
                                       uint32_t addr) {
    asm volatile("ldmatrix.sync.aligned.m8n8.x4.trans.shared.b16 {%0,%1,%2,%3}, [%4];"
                 : "=r"(r0), "=r"(r1), "=r"(r2), "=r"(r3) : "r"(addr));
}
// fp16 inputs, fp32 accumulate
__device__ __forceinline__ void mma16816(float* c,
                                         uint32_t a0, uint32_t a1, uint32_t a2, uint32_t a3,
                                         uint32_t b0, uint32_t b1) {
    asm volatile("mma.sync.aligned.m16n8k16.row.col.f32.f16.f16.f32 "
                 "{%0,%1,%2,%3}, {%4,%5,%6,%7}, {%8,%9}, {%0,%1,%2,%3};"
                 : "+f"(c[0]), "+f"(c[1]), "+f"(c[2]), "+f"(c[3])
                 : "r"(a0), "r"(a1), "r"(a2), "r"(a3), "r"(b0), "r"(b1));
}
__device__ __forceinline__ uint32_t packsplit(float v0, float v1, uint32_t& lo) {
    __half2 hp = __floats2half2_rn(v0, v1);
    float2 hf = __half22float2(hp);
    __half2 lp = __floats2half2_rn(v0 - hf.x, v1 - hf.y);
    lo = *reinterpret_cast<uint32_t*>(&lp);
    return *reinterpret_cast<uint32_t*>(&hp);
}
__device__ __forceinline__ uint32_t packh2(float v0, float v1) {
    __half2 hp = __floats2half2_rn(v0, v1);
    return *reinterpret_cast<uint32_t*>(&hp);
}

// ---------------------------------------------------------------------------
// fp16 HMMA GEMM body, 128x256 CTA tile: C = (Ah [+ Al]) @ Bh. B staged via
// cp.async + ldsm (R16 measured: per-lane direct-B LDG costs ~8 L1tex
// wavefronts per instruction — strictly worse; keep the coalesced smem path).
// USE_AL=1 (2-product): 512 rows/chunk — MMA-bound (4096 vs 4096 cyc).
// USE_AL=0 (1-product): 384 rows/chunk — load-bound 3072 cyc (25% faster/chunk).
// 8 warps as 2m x 4n (warp tile 64x64). 4-stage ring, one sync per chunk.
// ---------------------------------------------------------------------------
constexpr int APITCH_B = 80;

template <bool USE_AL>
__device__ __forceinline__ void gemm_mma_body(
    const __half* __restrict__ Ahi, const __half* __restrict__ Alo,
    const __half* __restrict__ Bhi,
    int rowBase, int colBase, char* sm, float acc[4][8][4])
{
    constexpr int SROWS   = USE_AL ? 512 : 384;       // Ah(128) [| Al(128)] | B(256)
    constexpr int AL_OFF  = 128 * APITCH_B;
    constexpr int B_OFF   = (USE_AL ? 256 : 128) * APITCH_B;
    constexpr int STAGE_B = SROWS * APITCH_B;
    constexpr int NT      = SROWS / 64;               // cp16 rounds (8 or 6)

    const int tid  = threadIdx.x;
    const int lane = tid & 31;
    const int w    = tid >> 5;
    const int wm   = (w >> 2) * 64;
    const int wn   = (w & 3) * 64;
    const uint32_t sb = smem_u32(sm);

    auto load_stage = [&](int s, int k0) {
        const uint32_t base = sb + s * STAGE_B;
        #pragma unroll
        for (int t = 0; t < NT; ++t) {
            const int idx = t * 256 + tid;
            const int r = idx >> 2, ch = idx & 3;
            const __half* src;
            int grow;
            if (r < 128)                 { src = Ahi; grow = rowBase + r; }
            else if (USE_AL && r < 256)  { src = Alo; grow = rowBase + r - 128; }
            else                         { src = Bhi; grow = colBase + r - (USE_AL ? 256 : 128); }
            cp16(base + r * APITCH_B + ch * 16,
                 src + (size_t)grow * D + k0 + ch * 8);
        }
    };

    auto comp = [&](int s) {
        const uint32_t base = sb + s * STAGE_B;
        #pragma unroll
        for (int k16 = 0; k16 < 2; ++k16) {
            uint32_t Ah[4][4], Al[4][4];
            #pragma unroll
            for (int mi = 0; mi < 4; ++mi) {
                const uint32_t addr = base + (wm + mi * 16 + (lane & 15)) * APITCH_B
                                      + k16 * 32 + (lane >> 4) * 16;
                ldsm4(Ah[mi][0], Ah[mi][1], Ah[mi][2], Ah[mi][3], addr);
                if (USE_AL)
                    ldsm4(Al[mi][0], Al[mi][1], Al[mi][2], Al[mi][3], addr + AL_OFF);
            }
            #pragma unroll
            for (int np = 0; np < 4; ++np) {
                uint32_t Bh[4];
                const int nrow = wn + np * 16 + (lane & 7) + ((lane >> 4) << 3);
                const uint32_t addr = base + B_OFF + nrow * APITCH_B
                                      + k16 * 32 + ((lane >> 3) & 1) * 16;
                ldsm4(Bh[0], Bh[1], Bh[2], Bh[3], addr);
                #pragma unroll
                for (int mi = 0; mi < 4; ++mi)
                    #pragma unroll
                    for (int h2 = 0; h2 < 2; ++h2)
                        mma16816(acc[mi][np * 2 + h2],
                                 Ah[mi][0], Ah[mi][1], Ah[mi][2], Ah[mi][3],
                                 Bh[h2 * 2], Bh[h2 * 2 + 1]);
                if (USE_AL) {
                    #pragma unroll
                    for (int mi = 0; mi < 4; ++mi)
                        #pragma unroll
                        for (int h2 = 0; h2 < 2; ++h2)
                            mma16816(acc[mi][np * 2 + h2],
                                     Al[mi][0], Al[mi][1], Al[mi][2], Al[mi][3],
                                     Bh[h2 * 2], Bh[h2 * 2 + 1]);
                }
            }
        }
    };

    constexpr int NC = D / 32;   // 32 chunks
    load_stage(0, 0);            CP_COMMIT();
    load_stage(1, 32);           CP_COMMIT();
    load_stage(2, 64);           CP_COMMIT();
    for (int c = 0; c < NC; ++c) {
        CP_WAIT(2);
        __syncthreads();
        if (c + 3 < NC) load_stage((c + 3) & 3, (c + 3) * 32);
        CP_COMMIT();
        comp(c & 3);
    }
}

constexpr int GSMEM_QKV = 4 * 384 * APITCH_B;   // 122880
constexpr int GSMEM_OUT = 4 * 512 * APITCH_B;   // 163840

// QKV projection (1-product fp16, 128x256 tiles). Epilogue: Q pre-scaled QSCALE.
__global__ __launch_bounds__(256, 1) void qkv_mma() {
    extern __shared__ char sm[];
    const int z = blockIdx.z;
    const int rowBase = blockIdx.y * 128, colBase = blockIdx.x * 256;
    float acc[4][8][4];
    #pragma unroll
    for (int i = 0; i < 4; ++i)
        #pragma unroll
        for (int j = 0; j < 8; ++j)
            #pragma unroll
            for (int k = 0; k < 4; ++k) acc[i][j][k] = 0.f;

    gemm_mma_body<false>(g_Xhi, nullptr, g_WThi[z], rowBase, colBase, sm, acc);

    __half* Out = (z == 0) ? g_Qhi : (z == 1) ? g_Khi : g_Vhi;
    const float scale = (z == 0) ? QSCALE : 1.0f;
    const int lane = threadIdx.x & 31, w = threadIdx.x >> 5;
    const int wm = (w >> 2) * 64, wn = (w & 3) * 64;
    #pragma unroll
    for (int mi = 0; mi < 4; ++mi)
        #pragma unroll
        for (int nf = 0; nf < 8; ++nf) {
            const int r0 = rowBase + wm + mi * 16 + (lane >> 2);
            const int c0 = colBase + wn + nf * 8 + (lane & 3) * 2;
            const int hh = c0 >> 6, dd = c0 & 63;
            #pragma unroll
            for (int rr = 0; rr < 2; ++rr) {
                const int r = r0 + rr * 8;
                const int b = r >> 11, n = r & (N - 1);
                const size_t idx = (((size_t)(b * H + hh)) * N + n) * DK + dd;
                *reinterpret_cast<uint32_t*>(Out + idx) =
                    packh2(acc[mi][nf][rr * 2] * scale, acc[mi][nf][rr * 2 + 1] * scale);
            }
        }
}

// Output projection (2-product, AT-corrected): (AThi + ATlo) @ Wo -> fp32
__global__ __launch_bounds__(256, 1) void out_mma(float* __restrict__ Cout) {
    extern __shared__ char sm[];
    const int rowBase = blockIdx.y * 128, colBase = blockIdx.x * 256;
    float acc[4][8][4];
    #pragma unroll
    for (int i = 0; i < 4; ++i)
        #pragma unroll
        for (int j = 0; j < 8; ++j)
            #pragma unroll
            for (int k = 0; k < 4; ++k) acc[i][j][k] = 0.f;

    gemm_mma_body<true>(g_AThi, g_ATlo, g_WThi[3], rowBase, colBase, sm, acc);

    const int lane = threadIdx.x & 31, w = threadIdx.x >> 5;
    const int wm = (w >> 2) * 64, wn = (w & 3) * 64;
    #pragma unroll
    for (int mi = 0; mi < 4; ++mi)
        #pragma unroll
        for (int nf = 0; nf < 8; ++nf) {
            const int r0 = rowBase + wm + mi * 16 + (lane >> 2);
            const int c0 = colBase + wn + nf * 8 + (lane & 3) * 2;
            #pragma unroll
            for (int e = 0; e < 4; ++e)
                Cout[(size_t)(r0 + (e >> 1) * 8) * HD + c0 + (e & 1)] = acc[mi][nf][e];
        }
}

// ---------------------------------------------------------------------------
// Conversion passes
// ---------------------------------------------------------------------------
__global__ void convX(const float* __restrict__ X) {
    const size_t i = ((size_t)blockIdx.x * 256 + threadIdx.x) * 4;
    const float4 v = *(const float4*)(X + i);
    uint2 pk; pk.x = packh2(v.x, v.y); pk.y = packh2(v.z, v.w);
    *reinterpret_cast<uint2*>(g_Xhi + i) = pk;
}

// Transpose W -> WT[n][k], fp16
__global__ void convW(const float* __restrict__ Wq, const float* __restrict__ Wk,
                      const float* __restrict__ Wv, const float* __restrict__ Wo) {
    const int z = blockIdx.z;
    const float* W = (z == 0) ? Wq : (z == 1) ? Wk : (z == 2) ? Wv : Wo;
    __half* Th = g_WThi[z];
    __shared__ float t[32][33];
    const int k0 = blockIdx.x * 32, n0 = blockIdx.y * 32;
    #pragma unroll
    for (int j = 0; j < 32; j += 8)
        t[threadIdx.y + j][threadIdx.x] = W[(size_t)(k0 + threadIdx.y + j) * HD + n0 + threadIdx.x];
    __syncthreads();
    #pragma unroll
    for (int j = 0; j < 32; j += 8) {
        const int n = n0 + threadIdx.y + j, k = k0 + threadIdx.x;
        Th[(size_t)n * D + k] = __float2half_rn(t[threadIdx.x][threadIdx.y + j]);
    }
}

// ---------------------------------------------------------------------------
// Tensor-core flash attention (causal):
// S = Qh*Kh (1-product; Q pre-scaled by log2e/8 -> logits in log2 domain,
// softmax via exp2f — saves the per-element log2e multiply; R16-measured win).
// O = Ph*Vh + Pl*Vh (2-product — 1-product PV exposed trans-LDSM latency
//   at 2 warps/SMSP; R12 regression).
// 128 q-rows per CTA, 8 warps. 3-stage KV ring (Kh|Vh), f32 acc.
// ---------------------------------------------------------------------------
constexpr int FP     = 144;            // smem pitch (128B data + 16B pad)
constexpr int KVARR  = 64 * FP;        // 9216
constexpr int KVSTG  = 2 * KVARR;      // Kh|Vh: 18432
constexpr int QARR   = 128 * FP;       // 18432
constexpr int FSTAGES = 3;
constexpr int FSMEM  = QARR + FSTAGES * KVSTG;   // 73728

__global__ __launch_bounds__(256, 1)
void flash_mma() {
    extern __shared__ char sm[];
    const uint32_t sb = smem_u32(sm);
    const int tid = threadIdx.x, lane = tid & 31, w = tid >> 5;
    const int bh = blockIdx.y;
    const int qt = gridDim.x - 1 - blockIdx.x;        // long blocks first
    const int q0 = qt * 128;
    const int b = bh >> 4, h = bh & (H - 1);
    const int wm = w * 16;

    const __half* Qh = g_Qhi + (size_t)bh * N * DK;
    const __half* Kh = g_Khi + (size_t)bh * N * DK;
    const __half* Vh = g_Vhi + (size_t)bh * N * DK;

    const uint32_t qhiS = sb, stS = sb + QARR;

    auto load_kv = [&](int s, int j0) {
        const uint32_t base = stS + s * KVSTG;
        #pragma unroll
        for (int t = 0; t < 2; ++t) {
            const int i = tid + t * 256;
            const int r = i >> 3, ch = i & 7;
            const uint32_t off = r * FP + ch * 16;
            const size_t gi = (size_t)(j0 + r) * DK + ch * 8;
            cp16(base + off,         Kh + gi);
            cp16(base + KVARR + off, Vh + gi);
        }
    };

    const int jmax = 2 * qt + 1;

    for (int i = tid; i < 1024; i += 256) {
        const int r = i >> 3, ch = i & 7;
        cp16(qhiS + r * FP + ch * 16, Qh + (size_t)(q0 + r) * DK + ch * 8);
    }
    load_kv(0, 0);
    CP_COMMIT();
    load_kv(1, 64);
    CP_COMMIT();

    float m0 = -1e30f, m1 = -1e30f, l0 = 0.f, l1 = 0.f;
    float oAcc[8][4];
    #pragma unroll
    for (int i = 0; i < 8; ++i)
        #pragma unroll
        for (int e = 0; e < 4; ++e) oAcc[i][e] = 0.f;

    uint32_t qah[4][4];
    bool qloaded = false;
    int kvbuf = 0;

    for (int jt = 0; jt <= jmax; ++jt) {
        const int j0 = jt * 64;
        CP_WAIT(1);
        __syncthreads();
        if (jt + 2 <= jmax) {
            int nb = kvbuf + 2; if (nb >= 3) nb -= 3;
            load_kv(nb, (jt + 2) * 64);
        }
        CP_COMMIT();

        if (!qloaded) {
            #pragma unroll
            for (int kf = 0; kf < 4; ++kf) {
                const uint32_t addr = qhiS + (wm + (lane & 15)) * FP + kf * 32 + (lane >> 4) * 16;
                ldsm4(qah[kf][0], qah[kf][1], qah[kf][2], qah[kf][3], addr);
            }
            qloaded = true;
        }

        const uint32_t khS = stS + kvbuf * KVSTG;
        const uint32_t vhS = khS + KVARR;
        if (++kvbuf == 3) kvbuf = 0;

        // ---- S = Qh @ Kh^T (1-product, log2-domain logits) ----
        float s[8][4];
        #pragma unroll
        for (int i = 0; i < 8; ++i)
            #pragma unroll
            for (int e = 0; e < 4; ++e) s[i][e] = 0.f;

        #pragma unroll
        for (int kf = 0; kf < 4; ++kf) {
            uint32_t kb[4][4];
            #pragma unroll
            for (int ng = 0; ng < 4; ++ng) {
                const uint32_t addr = khS + (ng * 16 + (lane & 7) + ((lane >> 4) << 3)) * FP
                                      + kf * 32 + ((lane >> 3) & 1) * 16;
                ldsm4(kb[ng][0], kb[ng][1], kb[ng][2], kb[ng][3], addr);
            }
            #pragma unroll
            for (int ng = 0; ng < 4; ++ng)
                #pragma unroll
                for (int nf = 0; nf < 2; ++nf)
                    mma16816(s[ng * 2 + nf], qah[kf][0], qah[kf][1], qah[kf][2], qah[kf][3],
                             kb[ng][nf * 2], kb[ng][nf * 2 + 1]);
        }

        // ---- causal mask ----
        const int gr0 = q0 + wm + (lane >> 2);
        if (j0 + 64 > q0 + wm) {
            #pragma unroll
            for (int ni = 0; ni < 8; ++ni)
                #pragma unroll
                for (int e = 0; e < 4; ++e) {
                    const int col = j0 + ni * 8 + (lane & 3) * 2 + (e & 1);
                    const int row = gr0 + (e >> 1) * 8;
                    if (col > row) s[ni][e] = -1e30f;
                }
        }

        // ---- online softmax (exp2 domain) ----
        float rm0 = -1e30f, rm1 = -1e30f;
        #pragma unroll
        for (int ni = 0; ni < 8; ++ni) {
            rm0 = fmaxf(rm0, fmaxf(s[ni][0], s[ni][1]));
            rm1 = fmaxf(rm1, fmaxf(s[ni][2], s[ni][3]));
        }
        rm0 = fmaxf(rm0, __shfl_xor_sync(0xffffffffu, rm0, 1));
        rm0 = fmaxf(rm0, __shfl_xor_sync(0xffffffffu, rm0, 2));
        rm1 = fmaxf(rm1, __shfl_xor_sync(0xffffffffu, rm1, 1));
        rm1 = fmaxf(rm1, __shfl_xor_sync(0xffffffffu, rm1, 2));

        const float mn0 = fmaxf(m0, rm0), mn1 = fmaxf(m1, rm1);
        const float a0 = exp2f(m0 - mn0), a1 = exp2f(m1 - mn1);
        m0 = mn0; m1 = mn1;

        float rs0 = 0.f, rs1 = 0.f;
        #pragma unroll
        for (int ni = 0; ni < 8; ++ni) {
            s[ni][0] = exp2f(s[ni][0] - mn0); rs0 += s[ni][0];
            s[ni][1] = exp2f(s[ni][1] - mn0); rs0 += s[ni][1];
            s[ni][2] = exp2f(s[ni][2] - mn1); rs1 += s[ni][2];
            s[ni][3] = exp2f(s[ni][3] - mn1); rs1 += s[ni][3];
        }
        rs0 += __shfl_xor_sync(0xffffffffu, rs0, 1);
        rs0 += __shfl_xor_sync(0xffffffffu, rs0, 2);
        rs1 += __shfl_xor_sync(0xffffffffu, rs1, 1);
        rs1 += __shfl_xor_sync(0xffffffffu, rs1, 2);
        l0 = l0 * a0 + rs0;
        l1 = l1 * a1 + rs1;

        #pragma unroll
        for (int ni = 0; ni < 8; ++ni) {
            oAcc[ni][0] *= a0; oAcc[ni][1] *= a0;
            oAcc[ni][2] *= a1; oAcc[ni][3] *= a1;
        }

        // ---- P -> fp16 hi/lo A-fragments (register-only) ----
        uint32_t pah[4][4], pal[4][4];
        #pragma unroll
        for (int kf = 0; kf < 4; ++kf) {
            pah[kf][0] = packsplit(s[2 * kf][0],     s[2 * kf][1],     pal[kf][0]);
            pah[kf][1] = packsplit(s[2 * kf][2],     s[2 * kf][3],     pal[kf][1]);
            pah[kf][2] = packsplit(s[2 * kf + 1][0], s[2 * kf + 1][1], pal[kf][2]);
            pah[kf][3] = packsplit(s[2 * kf + 1][2], s[2 * kf + 1][3], pal[kf][3]);
        }

        // ---- O += (Ph + Pl) @ Vh ----
        #pragma unroll
        for (int kf = 0; kf < 4; ++kf) {
            uint32_t vb[4][4];
            #pragma unroll
            for (int ng = 0; ng < 4; ++ng) {
                const uint32_t addr = vhS + (kf * 16 + (lane & 15)) * FP
                                      + ng * 32 + (lane >> 4) * 16;
                ldsm4t(vb[ng][0], vb[ng][1], vb[ng][2], vb[ng][3], addr);
            }
            #pragma unroll
            for (int ng = 0; ng < 4; ++ng)
                #pragma unroll
                for (int nf = 0; nf < 2; ++nf)
                    mma16816(oAcc[ng * 2 + nf], pah[kf][0], pah[kf][1], pah[kf][2], pah[kf][3],
                             vb[ng][nf * 2], vb[ng][nf * 2 + 1]);
            #pragma unroll
            for (int ng = 0; ng < 4; ++ng)
                #pragma unroll
                for (int nf = 0; nf < 2; ++nf)
                    mma16816(oAcc[ng * 2 + nf], pal[kf][0], pal[kf][1], pal[kf][2], pal[kf][3],
                             vb[ng][nf * 2], vb[ng][nf * 2 + 1]);
        }
        // no trailing sync: 3-stage ring + top-of-loop barrier covers reuse
    }

    // ---- epilogue: normalize, split to fp16 hi/lo for output projection ----
    const float inv0 = 1.0f / l0, inv1 = 1.0f / l1;
    const int r0 = q0 + wm + (lane >> 2);
    #pragma unroll
    for (int ni = 0; ni < 8; ++ni) {
        const int col = h * DK + ni * 8 + (lane & 3) * 2;
        uint32_t lo;
        uint32_t hi = packsplit(oAcc[ni][0] * inv0, oAcc[ni][1] * inv0, lo);
        size_t idx = ((size_t)b * N + r0) * HD + col;
        *reinterpret_cast<uint32_t*>(g_AThi + idx) = hi;
        *reinterpret_cast<uint32_t*>(g_ATlo + idx) = lo;
        hi = packsplit(oAcc[ni][2] * inv1, oAcc[ni][3] * inv1, lo);
        idx = ((size_t)b * N + r0 + 8) * HD + col;
        *reinterpret_cast<uint32_t*>(g_AThi + idx) = hi;
        *reinterpret_cast<uint32_t*>(g_ATlo + idx) = lo;
    }
}

// ---------------------------------------------------------------------------
extern "C" void kernel_launch(void* const* d_in, const int* in_sizes, int n_in,
                              void* d_out, int out_size) {
    const float* X  = (const float*)d_in[0];
    // d_in[1] = mask (pure causal -> applied analytically)
    const float* Wq = (const float*)d_in[2];
    const float* Wk = (const float*)d_in[3];
    const float* Wv = (const float*)d_in[4];
    const float* Wo = (const float*)d_in[5];
    float* out = (float*)d_out;

    cudaFuncSetAttribute(qkv_mma,   cudaFuncAttributeMaxDynamicSharedMemorySize, GSMEM_QKV);
    cudaFuncSetAttribute(out_mma,   cudaFuncAttributeMaxDynamicSharedMemorySize, GSMEM_OUT);
    cudaFuncSetAttribute(flash_mma, cudaFuncAttributeMaxDynamicSharedMemorySize, FSMEM);

    // 0) conversions
    convX<<<(B * N * D / 4) / 256, 256>>>(X);
    convW<<<dim3(D / 32, HD / 32, 4), dim3(32, 8)>>>(Wq, Wk, Wv, Wo);

    // 1) QKV projections (1-product fp16, 128x256 tiles, smem-staged B)
    qkv_mma<<<dim3(HD / 256, (B * N) / 128, 3), 256, GSMEM_QKV>>>();   // (4, 64, 3)

    // 2) causal flash attention (S 1-product + exp2, PV 2-product)
    flash_mma<<<dim3(N / 128, B * H), 256, FSMEM>>>();                 // (16, 64)

    // 3) output projection (2-product, AT-corrected, smem-staged B)
    out_mma<<<dim3(HD / 256, (B * N) / 128), 256, GSMEM_OUT>>>(out);   // (4, 64)
}